// round 2
// baseline (speedup 1.0000x reference)
#include <cuda_runtime.h>

#define NF    22528          // NUM_FEATURES
#define NOUT  520            // HIDDEN + BUCKET_NB
#define HID   512
#define NROWS 8192
#define NB    8              // buckets
#define MAXIDX 512
#define BPB   64             // blocks per bucket in MLP kernel
#define SCALE_O 400.0f

// Scratch (allowed: __device__ globals, no runtime allocation)
__device__ float g_WftT[(size_t)NF * NOUT];       // 46.9 MB transposed weights
__device__ float g_x[(size_t)NROWS * 1024];       // 32 MB clipped activations
__device__ float g_psqt[NROWS];
__device__ int   g_rows[NB * NROWS];
__device__ int   g_cnt[NB];

// ---------------------------------------------------------------------------
// Kernel A: zero per-bucket counters
// ---------------------------------------------------------------------------
__global__ void zero_cnt() {
    if (threadIdx.x < NB) g_cnt[threadIdx.x] = 0;
}

// ---------------------------------------------------------------------------
// Kernel B: transpose W_ft [520, 22528] -> g_WftT [22528, 520]
// ---------------------------------------------------------------------------
__global__ void transpose_wft(const float* __restrict__ W) {
    __shared__ float tile[32][33];
    int f0 = blockIdx.x * 32;
    int o0 = blockIdx.y * 32;
    int tx = threadIdx.x;   // 0..31
    int ty = threadIdx.y;   // 0..7
#pragma unroll
    for (int i = 0; i < 4; i++) {
        int o = o0 + ty + 8 * i;
        float v = 0.0f;
        if (o < NOUT) v = W[(size_t)o * NF + f0 + tx];
        tile[ty + 8 * i][tx] = v;
    }
    __syncthreads();
#pragma unroll
    for (int i = 0; i < 4; i++) {
        int f = f0 + ty + 8 * i;
        int o = o0 + tx;
        if (o < NOUT)
            g_WftT[(size_t)f * NOUT + o] = tile[tx][ty + 8 * i];
    }
}

// ---------------------------------------------------------------------------
// Kernel C: per-row scan + sparse accumulate + clip -> g_x, psqt, bucket list
// ---------------------------------------------------------------------------
__device__ __forceinline__ float clip01(float v) {
    return fminf(fmaxf(v, 0.0f), 1.0f);
}

__global__ __launch_bounds__(256, 8) void nnue_acc(
    const float* __restrict__ wf,      // [8192, 22528]
    const float* __restrict__ bfeat,   // [8192, 22528]
    const float* __restrict__ stm_arr, // [8192, 1]
    const int*   __restrict__ buckets, // [8192]
    const float* __restrict__ b_ft)    // [520]
{
    __shared__ int s_idxW[MAXIDX];
    __shared__ int s_idxB[MAXIDX];
    __shared__ int s_cntW, s_cntB;

    const int row = blockIdx.x;
    const int tid = threadIdx.x;

    if (tid == 0) { s_cntW = 0; s_cntB = 0; }
    __syncthreads();

    // ---- Phase A: stream-scan both feature rows, collect active indices ----
    {
        const float4* w4 = (const float4*)(wf    + (size_t)row * NF);
        const float4* b4 = (const float4*)(bfeat + (size_t)row * NF);
#pragma unroll 2
        for (int u = tid; u < NF / 4; u += 256) {
            float4 v = __ldcs(&w4[u]);           // streaming: don't hold in L2
            float4 q = __ldcs(&b4[u]);
            if (v.x != 0.0f) { int p = atomicAdd(&s_cntW, 1); if (p < MAXIDX) s_idxW[p] = 4 * u + 0; }
            if (v.y != 0.0f) { int p = atomicAdd(&s_cntW, 1); if (p < MAXIDX) s_idxW[p] = 4 * u + 1; }
            if (v.z != 0.0f) { int p = atomicAdd(&s_cntW, 1); if (p < MAXIDX) s_idxW[p] = 4 * u + 2; }
            if (v.w != 0.0f) { int p = atomicAdd(&s_cntW, 1); if (p < MAXIDX) s_idxW[p] = 4 * u + 3; }
            if (q.x != 0.0f) { int p = atomicAdd(&s_cntB, 1); if (p < MAXIDX) s_idxB[p] = 4 * u + 0; }
            if (q.y != 0.0f) { int p = atomicAdd(&s_cntB, 1); if (p < MAXIDX) s_idxB[p] = 4 * u + 1; }
            if (q.z != 0.0f) { int p = atomicAdd(&s_cntB, 1); if (p < MAXIDX) s_idxB[p] = 4 * u + 2; }
            if (q.w != 0.0f) { int p = atomicAdd(&s_cntB, 1); if (p < MAXIDX) s_idxB[p] = 4 * u + 3; }
        }
    }
    __syncthreads();
    const int cw = min(s_cntW, MAXIDX);
    const int cb = min(s_cntB, MAXIDX);
    const int k  = buckets[row];

    // ---- Phase B: register accumulators (thread t owns cols 2t, 2t+1) ----
    float2 aw = *(const float2*)(b_ft + 2 * tid);
    float2 ab = aw;
    float psw = 0.0f, psb = 0.0f;   // b_ft cancels in psqt difference

#pragma unroll 4
    for (int i = 0; i < cw; i++) {
        const float* r = g_WftT + (size_t)s_idxW[i] * NOUT;
        float2 v = *(const float2*)(r + 2 * tid);
        aw.x += v.x; aw.y += v.y;
        if (tid == 0) psw += r[512 + k];
    }
#pragma unroll 4
    for (int i = 0; i < cb; i++) {
        const float* r = g_WftT + (size_t)s_idxB[i] * NOUT;
        float2 v = *(const float2*)(r + 2 * tid);
        ab.x += v.x; ab.y += v.y;
        if (tid == 0) psb += r[512 + k];
    }

    // ---- Phase C: stm-ordered clip, write x directly from registers ----
    const float stm = stm_arr[row];           // exactly 0.0 or 1.0
    const bool wfirst = (stm == 0.0f);
    float2 xf = wfirst ? aw : ab;
    float2 xs = wfirst ? ab : aw;

    float2* xr = (float2*)(g_x + (size_t)row * 1024);
    xr[tid]       = make_float2(clip01(xf.x), clip01(xf.y));
    xr[256 + tid] = make_float2(clip01(xs.x), clip01(xs.y));

    if (tid == 0) {
        g_psqt[row] = (psw - psb) * (0.5f - stm);
        int p = atomicAdd(&g_cnt[k], 1);
        g_rows[k * NROWS + p] = row;
    }
}

// ---------------------------------------------------------------------------
// Kernel D: bucket-batched MLP. 64 blocks per bucket; W1k cached in smem.
// ---------------------------------------------------------------------------
__global__ __launch_bounds__(256, 1) void nnue_mlp(
    const float* __restrict__ W1,   // [8, 32, 1024]
    const float* __restrict__ b1,   // [8, 32]
    const float* __restrict__ W2,   // [8, 32, 32]
    const float* __restrict__ b2,   // [8, 32]
    const float* __restrict__ W3,   // [8, 1, 32]
    const float* __restrict__ b3,   // [8, 1]
    float*       __restrict__ out)  // [8192]
{
    extern __shared__ float smW1[];           // 32*1024 floats = 128 KB
    __shared__ float s_x[1024];
    __shared__ float s_h1[32];
    __shared__ float s_w2t[1024];             // W2k transposed: [i][o]

    const int k   = blockIdx.x / BPB;
    const int j0  = blockIdx.x % BPB;
    const int tid = threadIdx.x;
    const int warp = tid >> 5, lane = tid & 31;

    // Load W1k into smem (float4), W2k transposed
    {
        const float4* src = (const float4*)(W1 + (size_t)k * 32 * 1024);
        float4* dst = (float4*)smW1;
        for (int i = tid; i < 8192; i += 256) dst[i] = __ldg(&src[i]);
        for (int i = tid; i < 1024; i += 256) {
            int o = i >> 5, ii = i & 31;
            s_w2t[ii * 32 + o] = __ldg(&W2[k * 1024 + i]);
        }
    }
    __syncthreads();

    const int cnt = g_cnt[k];
    const float b3k = __ldg(&b3[k]);

    for (int j = j0; j < cnt; j += BPB) {
        const int row = g_rows[k * NROWS + j];

        // load x[1024] (float4 per thread)
        ((float4*)s_x)[tid] = __ldg(&((const float4*)(g_x + (size_t)row * 1024))[tid]);
        __syncthreads();

        // Layer 1: warp w computes outputs 4w..4w+3 via float4 dot
        const float4* x4 = (const float4*)s_x;
#pragma unroll
        for (int oo = 0; oo < 4; oo++) {
            const int o = warp * 4 + oo;
            const float4* w4 = (const float4*)(smW1 + o * 1024);
            float s = 0.0f;
#pragma unroll
            for (int jj = 0; jj < 8; jj++) {
                float4 xv = x4[jj * 32 + lane];     // conflict-free
                float4 wv = w4[jj * 32 + lane];
                s += xv.x * wv.x + xv.y * wv.y + xv.z * wv.z + xv.w * wv.w;
            }
#pragma unroll
            for (int d = 16; d; d >>= 1) s += __shfl_xor_sync(0xFFFFFFFFu, s, d);
            if (lane == 0) s_h1[o] = clip01(s + __ldg(&b1[k * 32 + o]));
        }
        __syncthreads();

        // Layers 2+3 + psqt + output: warp 0
        if (warp == 0) {
            float s = 0.0f;
#pragma unroll
            for (int i = 0; i < 32; i++)
                s += s_h1[i] * s_w2t[i * 32 + lane];   // conflict-free
            float h2 = clip01(s + __ldg(&b2[k * 32 + lane]));
            float p = h2 * __ldg(&W3[k * 32 + lane]);
#pragma unroll
            for (int d = 16; d; d >>= 1) p += __shfl_xor_sync(0xFFFFFFFFu, p, d);
            if (lane == 0)
                out[row] = (p + b3k + g_psqt[row]) * SCALE_O;
        }
        __syncthreads();
    }
}

// ---------------------------------------------------------------------------
// Harness entry
// ---------------------------------------------------------------------------
extern "C" void kernel_launch(void* const* d_in, const int* in_sizes, int n_in,
                              void* d_out, int out_size) {
    const float* wf    = (const float*)d_in[0];
    const float* bfeat = (const float*)d_in[1];
    const float* stm   = (const float*)d_in[2];
    const int*   bkt   = (const int*)  d_in[3];
    const float* W_ft  = (const float*)d_in[4];
    const float* b_ft  = (const float*)d_in[5];
    const float* W1    = (const float*)d_in[6];
    const float* b1    = (const float*)d_in[7];
    const float* W2    = (const float*)d_in[8];
    const float* b2    = (const float*)d_in[9];
    const float* W3    = (const float*)d_in[10];
    const float* b3    = (const float*)d_in[11];
    float* out = (float*)d_out;

    static bool attr_done = false;
    if (!attr_done) {
        cudaFuncSetAttribute(nnue_mlp, cudaFuncAttributeMaxDynamicSharedMemorySize,
                             32 * 1024 * sizeof(float));
        attr_done = true;
    }

    zero_cnt<<<1, 32>>>();
    dim3 tg(NF / 32, (NOUT + 31) / 32);
    transpose_wft<<<tg, dim3(32, 8)>>>(W_ft);
    nnue_acc<<<NROWS, 256>>>(wf, bfeat, stm, bkt, b_ft);
    nnue_mlp<<<NB * BPB, 256, 32 * 1024 * sizeof(float)>>>(W1, b1, W2, b2, W3, b3, out);
}

// round 3
// speedup vs baseline: 1.3378x; 1.3378x over previous
#include <cuda_runtime.h>
#include <cuda_fp16.h>

#define NF    22528          // NUM_FEATURES
#define NOUT  520            // HIDDEN + BUCKET_NB
#define HID   512
#define NROWS 8192
#define NB    8
#define MAXIDX 512
#define SCALE_O 400.0f

// Scratch: fp16 transposed FT weights (23.4 MB) + fp16 W1 (512 KB)
__device__ __half g_WftTh[(size_t)NF * NOUT];
__device__ __half g_W1h[NB * 32 * 1024];

// ---------------------------------------------------------------------------
// Kernel A: transpose W_ft [520, 22528] -> g_WftTh [22528, 520] (fp16)
// ---------------------------------------------------------------------------
__global__ void transpose_wft(const float* __restrict__ W) {
    __shared__ float tile[32][33];
    int f0 = blockIdx.x * 32;
    int o0 = blockIdx.y * 32;
    int tx = threadIdx.x;   // 0..31
    int ty = threadIdx.y;   // 0..7
#pragma unroll
    for (int i = 0; i < 4; i++) {
        int o = o0 + ty + 8 * i;
        float v = 0.0f;
        if (o < NOUT) v = W[(size_t)o * NF + f0 + tx];
        tile[ty + 8 * i][tx] = v;
    }
    __syncthreads();
#pragma unroll
    for (int i = 0; i < 4; i++) {
        int f = f0 + ty + 8 * i;
        int o = o0 + tx;
        if (o < NOUT)
            g_WftTh[(size_t)f * NOUT + o] = __float2half_rn(tile[tx][ty + 8 * i]);
    }
}

// ---------------------------------------------------------------------------
// Kernel B: convert W1 to fp16
// ---------------------------------------------------------------------------
__global__ void conv_w1(const float* __restrict__ W1) {
    int i = blockIdx.x * 256 + threadIdx.x;   // 1024 blocks x 256 = 262144
    g_W1h[i] = __float2half_rn(W1[i]);
}

// ---------------------------------------------------------------------------
// Kernel C: integrated per-row NNUE
// ---------------------------------------------------------------------------
__device__ __forceinline__ float clip01(float v) {
    return fminf(fmaxf(v, 0.0f), 1.0f);
}

__global__ __launch_bounds__(256, 8) void nnue_row(
    const float* __restrict__ wf,      // [8192, 22528]
    const float* __restrict__ bfeat,   // [8192, 22528]
    const float* __restrict__ stm_arr, // [8192, 1]
    const int*   __restrict__ buckets, // [8192]
    const float* __restrict__ b_ft,    // [520]
    const float* __restrict__ b1,      // [8, 32]
    const float* __restrict__ W2,      // [8, 32, 32]
    const float* __restrict__ b2,      // [8, 32]
    const float* __restrict__ W3,      // [8, 1, 32]
    const float* __restrict__ b3,      // [8, 1]
    float*       __restrict__ out)     // [8192]
{
    __shared__ int   s_idxW[MAXIDX];
    __shared__ int   s_idxB[MAXIDX];
    __shared__ int   s_cntW, s_cntB;
    __shared__ float s_x[1024];
    __shared__ float s_h1[32];

    const int row = blockIdx.x;
    const int tid = threadIdx.x;

    if (tid == 0) { s_cntW = 0; s_cntB = 0; }
    __syncthreads();

    // ---- Phase A: stream-scan both feature rows, collect active indices ----
    {
        const float4* w4 = (const float4*)(wf    + (size_t)row * NF);
        const float4* b4 = (const float4*)(bfeat + (size_t)row * NF);
#pragma unroll 2
        for (int u = tid; u < NF / 4; u += 256) {
            float4 v = __ldcs(&w4[u]);
            float4 q = __ldcs(&b4[u]);
            if (v.x != 0.0f) { int p = atomicAdd(&s_cntW, 1); if (p < MAXIDX) s_idxW[p] = 4 * u + 0; }
            if (v.y != 0.0f) { int p = atomicAdd(&s_cntW, 1); if (p < MAXIDX) s_idxW[p] = 4 * u + 1; }
            if (v.z != 0.0f) { int p = atomicAdd(&s_cntW, 1); if (p < MAXIDX) s_idxW[p] = 4 * u + 2; }
            if (v.w != 0.0f) { int p = atomicAdd(&s_cntW, 1); if (p < MAXIDX) s_idxW[p] = 4 * u + 3; }
            if (q.x != 0.0f) { int p = atomicAdd(&s_cntB, 1); if (p < MAXIDX) s_idxB[p] = 4 * u + 0; }
            if (q.y != 0.0f) { int p = atomicAdd(&s_cntB, 1); if (p < MAXIDX) s_idxB[p] = 4 * u + 1; }
            if (q.z != 0.0f) { int p = atomicAdd(&s_cntB, 1); if (p < MAXIDX) s_idxB[p] = 4 * u + 2; }
            if (q.w != 0.0f) { int p = atomicAdd(&s_cntB, 1); if (p < MAXIDX) s_idxB[p] = 4 * u + 3; }
        }
    }
    __syncthreads();
    const int cw = min(s_cntW, MAXIDX);
    const int cb = min(s_cntB, MAXIDX);
    const int k  = buckets[row];

    // ---- Phase B: register accumulators; fp16 gather (thread t: cols 2t,2t+1)
    float2 aw = *(const float2*)(b_ft + 2 * tid);
    float2 ab = aw;
    float psw = 0.0f, psb = 0.0f;    // b_ft cancels in the psqt difference

#pragma unroll 4
    for (int i = 0; i < cw; i++) {
        const __half* r = g_WftTh + (size_t)s_idxW[i] * NOUT;
        float2 v = __half22float2(*(const __half2*)(r + 2 * tid));
        aw.x += v.x; aw.y += v.y;
        if (tid == 0) psw += __half2float(r[512 + k]);
    }
#pragma unroll 4
    for (int i = 0; i < cb; i++) {
        const __half* r = g_WftTh + (size_t)s_idxB[i] * NOUT;
        float2 v = __half22float2(*(const __half2*)(r + 2 * tid));
        ab.x += v.x; ab.y += v.y;
        if (tid == 0) psb += __half2float(r[512 + k]);
    }

    // ---- Phase C: stm-ordered clip into x[1024] ----
    const float stm = stm_arr[row];   // exactly 0.0 or 1.0
    const bool wfirst = (stm == 0.0f);
    float2 xf = wfirst ? aw : ab;
    float2 xs = wfirst ? ab : aw;

    float2* x2 = (float2*)s_x;
    x2[tid]       = make_float2(clip01(xf.x), clip01(xf.y));
    x2[256 + tid] = make_float2(clip01(xs.x), clip01(xs.y));
    __syncthreads();

    // ---- Layer 1 (fp16 W1 from L2): warp w computes outputs 4w..4w+3 ----
    const int warp = tid >> 5, lane = tid & 31;
    const __half2* W1k = (const __half2*)(g_W1h + (size_t)k * 32 * 1024);
    const float2*  sx2 = (const float2*)s_x;
#pragma unroll
    for (int oo = 0; oo < 4; oo++) {
        const int o = warp * 4 + oo;
        const __half2* wr = W1k + o * 512;
        float s = 0.0f;
#pragma unroll
        for (int m = 0; m < 16; m++) {
            float2 xv = sx2[lane + 32 * m];                  // conflict-free
            float2 wv = __half22float2(__ldg(&wr[lane + 32 * m]));
            s += xv.x * wv.x + xv.y * wv.y;
        }
#pragma unroll
        for (int d = 16; d; d >>= 1) s += __shfl_xor_sync(0xFFFFFFFFu, s, d);
        if (lane == 0) s_h1[o] = clip01(s + __ldg(&b1[k * 32 + o]));
    }
    __syncthreads();

    // ---- Layers 2+3 + psqt + output: warp 0 ----
    if (warp == 0) {
        const float* W2k = W2 + k * 32 * 32;
        float s = 0.0f;
#pragma unroll
        for (int i = 0; i < 32; i++)
            s += s_h1[i] * __ldg(&W2k[lane * 32 + i]);
        float h2 = clip01(s + __ldg(&b2[k * 32 + lane]));

        float p = h2 * __ldg(&W3[k * 32 + lane]);
#pragma unroll
        for (int d = 16; d; d >>= 1) p += __shfl_xor_sync(0xFFFFFFFFu, p, d);

        if (lane == 0) {
            float psqt = (psw - psb) * (0.5f - stm);
            out[row] = (p + __ldg(&b3[k]) + psqt) * SCALE_O;
        }
    }
}

// ---------------------------------------------------------------------------
// Harness entry
// ---------------------------------------------------------------------------
extern "C" void kernel_launch(void* const* d_in, const int* in_sizes, int n_in,
                              void* d_out, int out_size) {
    const float* wf    = (const float*)d_in[0];
    const float* bfeat = (const float*)d_in[1];
    const float* stm   = (const float*)d_in[2];
    const int*   bkt   = (const int*)  d_in[3];
    const float* W_ft  = (const float*)d_in[4];
    const float* b_ft  = (const float*)d_in[5];
    const float* W1    = (const float*)d_in[6];
    const float* b1    = (const float*)d_in[7];
    const float* W2    = (const float*)d_in[8];
    const float* b2    = (const float*)d_in[9];
    const float* W3    = (const float*)d_in[10];
    const float* b3    = (const float*)d_in[11];
    float* out = (float*)d_out;

    dim3 tg(NF / 32, (NOUT + 31) / 32);
    transpose_wft<<<tg, dim3(32, 8)>>>(W_ft);
    conv_w1<<<1024, 256>>>(W1);
    nnue_row<<<NROWS, 256>>>(wf, bfeat, stm, bkt, b_ft,
                             b1, W2, b2, W3, b3, out);
}